// round 11
// baseline (speedup 1.0000x reference)
#include <cuda_runtime.h>
#include <math_constants.h>

// out[c] = dequant(quant(x[c])); group membership permuted by perm.
// Block = 4 rows interleaved in smem (s4[c] = {r0..r3}[c], quad-swizzled).
// Warp w gathers permuted group w (prologue-sorted indices -> ~conflict-free
// LDS.128), reduces min/max for 4 rows, quantizes IN REGISTERS (params never
// leave the warp), scatters results back IN PLACE, then linear reread +
// STG.128. No param tables, no inv[] use, 64 KB smem -> 2 CTAs/SM.

#define ROW_C 4096
#define NT    1024
#define RPT   4
#define Q_MAX 15.0f
#define EPS   1e-5f

__device__ int g_sperm[ROW_C];

// float4-element quad swizzle: element i lives in bank-quad swz(i)&7
__device__ __forceinline__ int swz(int i) { return i ^ ((i >> 3) & 7); }

// One warp per group; closed-form dispersal over 8 swizzled-quad bins.
// Element with residue r = swz(p)&7, rank k<16 -> pos k*8+((r-k)&7);
// overflow ranks fill the exact complement holes. Within-bin order is
// nondeterministic but min/max reduction cannot observe it.
__global__ void sort_perm_kernel(const int* __restrict__ perm)
{
    __shared__ int emit [32][128];
    __shared__ int holes[32][128];
    __shared__ int cnt[32][8], rk[32][8];
    __shared__ int nhole[32], nov[32];

    const int w    = threadIdx.x >> 5;
    const int lane = threadIdx.x & 31;

    if (lane < 8) { cnt[w][lane] = 0; rk[w][lane] = 0; }
    if (lane == 0) { nhole[w] = 0; nov[w] = 0; }
    __syncwarp();

    int v[4];
    #pragma unroll
    for (int i = 0; i < 4; ++i) {
        v[i] = perm[w * 128 + i * 32 + lane];            // coalesced
        atomicAdd(&cnt[w][swz(v[i]) & 7], 1);
    }
    __syncwarp();

    // hole: p=c*8+s unfilled iff bin (s+c)&7 has cnt <= c
    #pragma unroll
    for (int i = 0; i < 4; ++i) {
        const int p = i * 32 + lane;
        const int c = p >> 3, s = p & 7;
        if (cnt[w][(s + c) & 7] <= c)
            holes[w][atomicAdd(&nhole[w], 1)] = p;
    }
    __syncwarp();

    #pragma unroll
    for (int i = 0; i < 4; ++i) {
        const int r = swz(v[i]) & 7;
        const int k = atomicAdd(&rk[w][r], 1);
        const int pos = (k < 16) ? (k * 8 + ((r - k) & 7))
                                 : holes[w][atomicAdd(&nov[w], 1)];
        emit[w][pos] = v[i];
    }
    __syncwarp();

    #pragma unroll
    for (int i = 0; i < 4; ++i)
        g_sperm[w * 128 + i * 32 + lane] = emit[w][i * 32 + lane];
}

extern __shared__ float4 smem_dyn[];

__global__ __launch_bounds__(NT, 2)
void tpq_kernel(const float* __restrict__ x,
                float*       __restrict__ out)
{
    float4* s4 = smem_dyn;                      // [4096] float4 = 64 KB

    const int t    = threadIdx.x;
    const int warp = t >> 5;
    const int lane = t & 31;
    const size_t rowbase = (size_t)blockIdx.x * (RPT * ROW_C);

    int pp[4];                                  // bank-dispersed gather idx
    #pragma unroll
    for (int i = 0; i < 4; ++i)
        pp[i] = g_sperm[warp * 128 + i * 32 + lane];

    // ---- 4 x LDG.128 (rows r0..r3, channels 4t..4t+3); stage swizzled ----
    {
        float4 a0 = __ldcs((const float4*)(x + rowbase)             + t);
        float4 a1 = __ldcs((const float4*)(x + rowbase +     ROW_C) + t);
        float4 a2 = __ldcs((const float4*)(x + rowbase + 2 * ROW_C) + t);
        float4 a3 = __ldcs((const float4*)(x + rowbase + 3 * ROW_C) + t);
        const float* p0 = (const float*)&a0;
        const float* p1 = (const float*)&a1;
        const float* p2 = (const float*)&a2;
        const float* p3 = (const float*)&a3;
        #pragma unroll
        for (int j = 0; j < 4; ++j)
            s4[swz(4 * t + j)] = make_float4(p0[j], p1[j], p2[j], p3[j]);
    }
    __syncthreads();

    // ---- gather permuted group w (4 rows per LDS.128) + reduce ----
    float4 v[4];
    float mn[RPT], mx[RPT];
    #pragma unroll
    for (int r = 0; r < RPT; ++r) { mn[r] = CUDART_INF_F; mx[r] = -CUDART_INF_F; }

    #pragma unroll
    for (int i = 0; i < 4; ++i) {
        v[i] = s4[swz(pp[i])];
        mn[0] = fminf(mn[0], v[i].x);  mx[0] = fmaxf(mx[0], v[i].x);
        mn[1] = fminf(mn[1], v[i].y);  mx[1] = fmaxf(mx[1], v[i].y);
        mn[2] = fminf(mn[2], v[i].z);  mx[2] = fmaxf(mx[2], v[i].z);
        mn[3] = fminf(mn[3], v[i].w);  mx[3] = fmaxf(mx[3], v[i].w);
    }
    #pragma unroll
    for (int off = 16; off; off >>= 1) {
        #pragma unroll
        for (int r = 0; r < RPT; ++r) {
            mn[r] = fminf(mn[r], __shfl_xor_sync(0xffffffffu, mn[r], off));
            mx[r] = fmaxf(mx[r], __shfl_xor_sync(0xffffffffu, mx[r], off));
        }
    }

    // ---- params in registers (warp-uniform), quantize, scatter in place ----
    float sc[RPT], is[RPT], bq[RPT];
    #pragma unroll
    for (int r = 0; r < RPT; ++r) {
        sc[r] = fmaxf(mx[r] - mn[r], EPS) / Q_MAX;
        is[r] = 1.0f / sc[r];
        bq[r] = fminf(fmaxf(rintf(-mn[r] * is[r]), 0.0f), Q_MAX);
    }
    #pragma unroll
    for (int i = 0; i < 4; ++i) {
        float4 q;
        q.x = fminf(fmaxf(rintf(v[i].x * is[0]), -bq[0]), Q_MAX - bq[0]) * sc[0];
        q.y = fminf(fmaxf(rintf(v[i].y * is[1]), -bq[1]), Q_MAX - bq[1]) * sc[1];
        q.z = fminf(fmaxf(rintf(v[i].z * is[2]), -bq[2]), Q_MAX - bq[2]) * sc[2];
        q.w = fminf(fmaxf(rintf(v[i].w * is[3]), -bq[3]), Q_MAX - bq[3]) * sc[3];
        s4[swz(pp[i])] = q;                     // same addresses, same warp
    }
    __syncthreads();

    // ---- linear reread (conflict-free) + 4 x STG.128 ----
    {
        float4 o0, o1, o2, o3;
        float* q0 = (float*)&o0;
        float* q1 = (float*)&o1;
        float* q2 = (float*)&o2;
        float* q3 = (float*)&o3;
        #pragma unroll
        for (int j = 0; j < 4; ++j) {
            const float4 w4 = s4[swz(4 * t + j)];
            q0[j] = w4.x;  q1[j] = w4.y;  q2[j] = w4.z;  q3[j] = w4.w;
        }
        __stcg((float4*)(out + rowbase)             + t, o0);
        __stcg((float4*)(out + rowbase +     ROW_C) + t, o1);
        __stcg((float4*)(out + rowbase + 2 * ROW_C) + t, o2);
        __stcg((float4*)(out + rowbase + 3 * ROW_C) + t, o3);
    }
}

extern "C" void kernel_launch(void* const* d_in, const int* in_sizes, int n_in,
                              void* d_out, int out_size)
{
    const float* x    = (const float*)d_in[0];
    const int*   perm = (const int*)d_in[1];
    float*       out  = (float*)d_out;

    sort_perm_kernel<<<1, NT>>>(perm);

    const int smem_bytes = ROW_C * sizeof(float4);       // 64 KB
    cudaFuncSetAttribute(tpq_kernel,
                         cudaFuncAttributeMaxDynamicSharedMemorySize, smem_bytes);

    const int rows = in_sizes[0] / ROW_C;                // 16384
    tpq_kernel<<<rows / RPT, NT, smem_bytes>>>(x, out);
}

// round 12
// speedup vs baseline: 1.1284x; 1.1284x over previous
#include <cuda_runtime.h>
#include <math_constants.h>

// out[c] = dequant(quant(x[c])); group membership permuted by perm.
// Block = 4 rows interleaved in smem (s4[c] = {r0..r3}[c], quad-swizzled).
// Warp w gathers permuted group w (prologue emits PRE-SWIZZLED, bank-
// dispersed indices -> ~conflict-free LDS.128), reduces min/max for 4 rows,
// then RE-GATHERS one element at a time to quantize and overwrite in place
// (no values held across the reduction -> no spills under the 32-reg cap).
// Linear reread + STG.128. No param tables, no inv[] use, 64 KB smem.

#define ROW_C 4096
#define NT    1024
#define RPT   4
#define Q_MAX 15.0f
#define EPS   1e-5f

__device__ int g_sperm[ROW_C];

// float4-element quad swizzle: element i lives in bank-quad swz(i)&7
__device__ __forceinline__ int swz(int i) { return i ^ ((i >> 3) & 7); }

// One warp per group; closed-form dispersal over 8 swizzled-quad bins.
// Element with residue r = swz(p)&7, rank k<16 -> pos k*8+((r-k)&7);
// overflow ranks fill the exact complement holes. Emits swz(p) directly.
// Within-bin order is nondeterministic but min/max cannot observe it.
__global__ void sort_perm_kernel(const int* __restrict__ perm)
{
    __shared__ int emit [32][128];
    __shared__ int holes[32][128];
    __shared__ int cnt[32][8], rk[32][8];
    __shared__ int nhole[32], nov[32];

    const int w    = threadIdx.x >> 5;
    const int lane = threadIdx.x & 31;

    if (lane < 8) { cnt[w][lane] = 0; rk[w][lane] = 0; }
    if (lane == 0) { nhole[w] = 0; nov[w] = 0; }
    __syncwarp();

    int v[4];
    #pragma unroll
    for (int i = 0; i < 4; ++i) {
        v[i] = swz(perm[w * 128 + i * 32 + lane]);       // pre-swizzled
        atomicAdd(&cnt[w][v[i] & 7], 1);
    }
    __syncwarp();

    // hole: p=c*8+s unfilled iff bin (s+c)&7 has cnt <= c
    #pragma unroll
    for (int i = 0; i < 4; ++i) {
        const int p = i * 32 + lane;
        const int c = p >> 3, s = p & 7;
        if (cnt[w][(s + c) & 7] <= c)
            holes[w][atomicAdd(&nhole[w], 1)] = p;
    }
    __syncwarp();

    #pragma unroll
    for (int i = 0; i < 4; ++i) {
        const int r = v[i] & 7;
        const int k = atomicAdd(&rk[w][r], 1);
        const int pos = (k < 16) ? (k * 8 + ((r - k) & 7))
                                 : holes[w][atomicAdd(&nov[w], 1)];
        emit[w][pos] = v[i];
    }
    __syncwarp();

    #pragma unroll
    for (int i = 0; i < 4; ++i)
        g_sperm[w * 128 + i * 32 + lane] = emit[w][i * 32 + lane];
}

extern __shared__ float4 smem_dyn[];

__global__ __launch_bounds__(NT, 2)
void tpq_kernel(const float* __restrict__ x,
                float*       __restrict__ out)
{
    float4* s4 = smem_dyn;                      // [4096] float4 = 64 KB

    const int t    = threadIdx.x;
    const int warp = t >> 5;
    const int lane = t & 31;
    const size_t rowbase = (size_t)blockIdx.x * (RPT * ROW_C);

    int pp[4];                                  // pre-swizzled gather idx
    #pragma unroll
    for (int i = 0; i < 4; ++i)
        pp[i] = g_sperm[warp * 128 + i * 32 + lane];

    // ---- 4 x LDG.128 (rows r0..r3, channels 4t..4t+3); stage swizzled ----
    {
        float4 a0 = __ldcs((const float4*)(x + rowbase)             + t);
        float4 a1 = __ldcs((const float4*)(x + rowbase +     ROW_C) + t);
        float4 a2 = __ldcs((const float4*)(x + rowbase + 2 * ROW_C) + t);
        float4 a3 = __ldcs((const float4*)(x + rowbase + 3 * ROW_C) + t);
        const float* p0 = (const float*)&a0;
        const float* p1 = (const float*)&a1;
        const float* p2 = (const float*)&a2;
        const float* p3 = (const float*)&a3;
        #pragma unroll
        for (int j = 0; j < 4; ++j)
            s4[swz(4 * t + j)] = make_float4(p0[j], p1[j], p2[j], p3[j]);
    }
    __syncthreads();

    // ---- gather (transient) + reduce min/max for 4 rows ----
    float mn[RPT], mx[RPT];
    #pragma unroll
    for (int r = 0; r < RPT; ++r) { mn[r] = CUDART_INF_F; mx[r] = -CUDART_INF_F; }

    #pragma unroll
    for (int i = 0; i < 4; ++i) {
        const float4 v = s4[pp[i]];             // ~conflict-free LDS.128
        mn[0] = fminf(mn[0], v.x);  mx[0] = fmaxf(mx[0], v.x);
        mn[1] = fminf(mn[1], v.y);  mx[1] = fmaxf(mx[1], v.y);
        mn[2] = fminf(mn[2], v.z);  mx[2] = fmaxf(mx[2], v.z);
        mn[3] = fminf(mn[3], v.w);  mx[3] = fmaxf(mx[3], v.w);
    }
    #pragma unroll
    for (int off = 16; off; off >>= 1) {
        #pragma unroll
        for (int r = 0; r < RPT; ++r) {
            mn[r] = fminf(mn[r], __shfl_xor_sync(0xffffffffu, mn[r], off));
            mx[r] = fmaxf(mx[r], __shfl_xor_sync(0xffffffffu, mx[r], off));
        }
    }

    // ---- params in registers (warp-uniform) ----
    float sc[RPT], is[RPT], bq[RPT];
    #pragma unroll
    for (int r = 0; r < RPT; ++r) {
        sc[r] = fmaxf(mx[r] - mn[r], EPS) / Q_MAX;
        is[r] = 1.0f / sc[r];
        bq[r] = fminf(fmaxf(rintf(-mn[r] * is[r]), 0.0f), Q_MAX);
    }

    // ---- re-gather, quantize, overwrite in place (one element live) ----
    #pragma unroll
    for (int i = 0; i < 4; ++i) {
        const float4 v = s4[pp[i]];
        float4 q;
        q.x = fminf(fmaxf(rintf(v.x * is[0]), -bq[0]), Q_MAX - bq[0]) * sc[0];
        q.y = fminf(fmaxf(rintf(v.y * is[1]), -bq[1]), Q_MAX - bq[1]) * sc[1];
        q.z = fminf(fmaxf(rintf(v.z * is[2]), -bq[2]), Q_MAX - bq[2]) * sc[2];
        q.w = fminf(fmaxf(rintf(v.w * is[3]), -bq[3]), Q_MAX - bq[3]) * sc[3];
        s4[pp[i]] = q;                          // same warp, same addresses
    }
    __syncthreads();

    // ---- linear reread (conflict-free) + 4 x STG.128 ----
    {
        float4 o0, o1, o2, o3;
        float* q0 = (float*)&o0;
        float* q1 = (float*)&o1;
        float* q2 = (float*)&o2;
        float* q3 = (float*)&o3;
        #pragma unroll
        for (int j = 0; j < 4; ++j) {
            const float4 w4 = s4[swz(4 * t + j)];
            q0[j] = w4.x;  q1[j] = w4.y;  q2[j] = w4.z;  q3[j] = w4.w;
        }
        __stcg((float4*)(out + rowbase)             + t, o0);
        __stcg((float4*)(out + rowbase +     ROW_C) + t, o1);
        __stcg((float4*)(out + rowbase + 2 * ROW_C) + t, o2);
        __stcg((float4*)(out + rowbase + 3 * ROW_C) + t, o3);
    }
}

extern "C" void kernel_launch(void* const* d_in, const int* in_sizes, int n_in,
                              void* d_out, int out_size)
{
    const float* x    = (const float*)d_in[0];
    const int*   perm = (const int*)d_in[1];
    float*       out  = (float*)d_out;

    sort_perm_kernel<<<1, NT>>>(perm);

    const int smem_bytes = ROW_C * sizeof(float4);       // 64 KB
    cudaFuncSetAttribute(tpq_kernel,
                         cudaFuncAttributeMaxDynamicSharedMemorySize, smem_bytes);

    const int rows = in_sizes[0] / ROW_C;                // 16384
    tpq_kernel<<<rows / RPT, NT, smem_bytes>>>(x, out);
}